// round 17
// baseline (speedup 1.0000x reference)
#include <cuda_runtime.h>

#define TSTEPS   2048
#define BLK      8
#define NB       (TSTEPS / BLK)   // 256
#define NREACH   16383
#define RDEPTH   8
#define SENT     0xFFFFFFFFu
#define DT_SUB_F 21600.0f
#define EPS_F    1e-6f

// Ring: 128 subtree roots (level 6) -> top CTA (level 7). Two uint4 per block.
__device__ uint4 g_ring[128][RDEPTH][2];

static __device__ __forceinline__ uint4 ld_rlx4(const uint4* p) {
    uint4 v;
    asm volatile("ld.relaxed.gpu.global.v4.b32 {%0,%1,%2,%3}, [%4];"
                 : "=r"(v.x), "=r"(v.y), "=r"(v.z), "=r"(v.w) : "l"(p) : "memory");
    return v;
}
static __device__ __forceinline__ void st_rlx4(uint4* p, uint4 v) {
    asm volatile("st.relaxed.gpu.global.v4.b32 [%0], {%1,%2,%3,%4};"
                 :: "l"(p), "r"(v.x), "r"(v.y), "r"(v.z), "r"(v.w) : "memory");
}
static __device__ __forceinline__ bool any_sent(uint4 v) {
    return (v.x == SENT) | (v.y == SENT) | (v.z == SENT) | (v.w == SENT);
}
static __device__ __forceinline__ bool all_sent(uint4 v) {
    return (v.x == SENT) & (v.y == SENT) & (v.z == SENT) & (v.w == SENT);
}
static __device__ __forceinline__ uint4 wait_data4(const uint4* p, uint4 v) {
    int tries = 0;
    while (any_sent(v)) {
        v = ld_rlx4(p);
        if (++tries > 8192) __nanosleep(64);
    }
    return v;
}
static __device__ __forceinline__ void wait_free4(uint4* p, uint4 v) {
    int tries = 0;
    while (!all_sent(v)) {
        v = ld_rlx4(p);
        if (++tries > 8192) __nanosleep(64);
    }
}

static __device__ __forceinline__ float ex2f_(float x){ float y; asm("ex2.approx.f32 %0, %1;" : "=f"(y) : "f"(x)); return y; }
static __device__ __forceinline__ float lg2f_(float x){ float y; asm("lg2.approx.f32 %0, %1;" : "=f"(y) : "f"(x)); return y; }
static __device__ __forceinline__ float rcpf_(float x){ float y; asm("rcp.approx.f32 %0, %1;" : "=f"(y) : "f"(x)); return y; }

__global__ void init_ring() {
    int i = blockIdx.x * blockDim.x + threadIdx.x;
    if (i < 128 * RDEPTH * 8) ((unsigned*)g_ring)[i] = SENT;
}

struct MCC { float negCE, kd, xc, xd; };

static __device__ __forceinline__ MCC mk_consts(
    int r, const float* logn, const float* lens, const float* slp,
    const float* wcs, const float* wes, const float* dcs, const float* des)
{
    MCC c;
    const float n_man = expf(logn[r]);
    const float dx = lens[r], S = slp[r];
    const float wc = wcs[r], we = wes[r], dc = dcs[r], de = des[r];
    const float cE   = (2.0f / 3.0f) * de;
    const float l2cB = log2f(5.0f / 3.0f) + 0.5f * log2f(S) - log2f(n_man)
                     + (2.0f / 3.0f) * log2f(dc);
    c.negCE = -cE;
    c.kd = log2f(2.0f * dx) - l2cB;            // 2K = ex2(negCE*lq + kd)
    c.xc = 1.0f - cE - we;                     // e2 = Qref/(2 c W S dx) = ex2(xc*lq + xd)
    c.xd = -(log2f(2.0f * S * dx) + l2cB + log2f(wc));
    return c;
}

// One timestep: 4 Muskingum-Cunge substeps.
// Substep 0 uses full form (io = Ip != Inew); substeps 1-3 use I == io == Inew:
//   q' = (2*dt*Inew + (B - dt) q) / (B + dt)   [A-terms cancel exactly]
// X-clip folded: B = 2K(1-X) = K2 * min(0.5 + e2, 1), e2 > 0 always.
static __device__ __forceinline__ float mc_timestep(float Inew, float& Ip, float q, MCC c) {
    const float u   = Inew + Ip;
    const float dlt = Ip - Inew;
    {
        const float Qref = fmaxf(fmaf(q, (1.0f/3.0f), u * (1.0f/3.0f)), EPS_F);
        const float lq = lg2f_(Qref);
        const float K2 = ex2f_(fmaf(c.negCE, lq, c.kd));
        const float e2 = ex2f_(fmaf(c.xc, lq, c.xd));
        const float Bf = fminf(0.5f + e2, 1.0f);
        const float B  = K2 * Bf;
        const float rD = rcpf_(B + DT_SUB_F);
        const float A  = K2 - B;
        const float acc = fmaf(DT_SUB_F, u - q, fmaf(A, dlt, B * q));
        q = fmaxf(acc * rD, 0.0f);
    }
    const float i23 = Inew * (2.0f/3.0f);
    const float c2  = (2.0f * DT_SUB_F) * Inew;
    #pragma unroll
    for (int s = 1; s < 4; ++s) {
        const float Qref = fmaxf(fmaf(q, (1.0f/3.0f), i23), EPS_F);
        const float lq = lg2f_(Qref);
        const float K2 = ex2f_(fmaf(c.negCE, lq, c.kd));
        const float e2 = ex2f_(fmaf(c.xc, lq, c.xd));
        const float Bf = fminf(0.5f + e2, 1.0f);
        const float B  = K2 * Bf;
        const float rD = rcpf_(B + DT_SUB_F);
        const float acc = fmaf(B - DT_SUB_F, q, c2);
        q = fmaxf(acc * rD, 0.0f);
    }
    Ip = Inew;
    return q;
}

__global__ void __launch_bounds__(128, 1) route_kernel(
    const float* __restrict__ lat,
    const float* __restrict__ logn,
    const float* __restrict__ lens,
    const float* __restrict__ slp,
    const float* __restrict__ wcs,
    const float* __restrict__ wes,
    const float* __restrict__ dcs,
    const float* __restrict__ des,
    float* __restrict__ out)
{
    __shared__ float sq[2][BLK][128];
    const int b   = blockIdx.x;
    const int tid = threadIdx.x;
    const uint4 SENT4 = {SENT, SENT, SENT, SENT};
    const int ITER = NB + 6;

    if (b < 128) {
        // ================= subtree CTA: levels 0..6, 127 reaches =================
        const bool active = (tid < 127);
        int l = 0, j = 0;
        if (active) {
            const unsigned u = 127 - tid;         // 1..127
            l = __clz(u) - 25;                    // 0..6
            j = tid - (128 - (128 >> l));
        }
        const int  r       = (16384 - (16384 >> l)) + b * (64 >> l) + j;
        const bool has_par = active && (l > 0);
        const int  cbase   = has_par ? (128 - (128 >> (l - 1))) : 0;
        const bool is_root = (tid == 126);        // level-6 root
        const int  skew    = l;

        MCC c = {};
        float Q = 0.f, Ip = 0.f;
        float lbuf[BLK];
        #pragma unroll
        for (int k = 0; k < BLK; ++k) lbuf[k] = 0.f;
        const float* latp = lat;
        if (active) {
            c = mk_consts(r, logn, lens, slp, wcs, wes, dcs, des);
            latp = lat + r;
            if (l == 0) {
                #pragma unroll
                for (int k = 0; k < BLK; ++k) lbuf[k] = __ldg(latp + (size_t)k * NREACH);
            }
        }

        for (int bi = 0; bi < ITER; ++bi) {
            const int tb = bi - skew;
            const int p  = bi & 1;
            const bool run = active && (tb >= 0) && (tb < NB);

            float ln[BLK];
            #pragma unroll
            for (int k = 0; k < BLK; ++k) ln[k] = 0.f;
            const int tbn = tb + 1;
            if (active && tbn >= 0 && tbn < NB) {
                const float* bp = latp + (size_t)(BLK * tbn) * NREACH;
                #pragma unroll
                for (int k = 0; k < BLK; ++k) ln[k] = __ldg(bp + (size_t)k * NREACH);
            }

            uint4 vfa = SENT4, vfb = SENT4;
            uint4* wslot = nullptr;
            if (run && is_root) {
                wslot = &g_ring[b][tb & (RDEPTH - 1)][0];
                vfa = ld_rlx4(wslot);
                vfb = ld_rlx4(wslot + 1);
            }

            if (run) {
                float qk[BLK];
                #pragma unroll
                for (int k = 0; k < BLK; ++k) {
                    float Inew = lbuf[k];
                    if (has_par)
                        Inew += sq[p ^ 1][k][cbase + 2 * j] + sq[p ^ 1][k][cbase + 2 * j + 1];
                    const float q = mc_timestep(Inew, Ip, Q, c);
                    Q = q;
                    qk[k] = q;
                    if (!is_root) sq[p][k][tid] = q;
                }
                if (is_root) {
                    wait_free4(wslot,     vfa);
                    wait_free4(wslot + 1, vfb);
                    uint4 pa, pb;
                    pa.x = __float_as_uint(qk[0]); pa.y = __float_as_uint(qk[1]);
                    pa.z = __float_as_uint(qk[2]); pa.w = __float_as_uint(qk[3]);
                    pb.x = __float_as_uint(qk[4]); pb.y = __float_as_uint(qk[5]);
                    pb.z = __float_as_uint(qk[6]); pb.w = __float_as_uint(qk[7]);
                    st_rlx4(wslot,     pa);
                    st_rlx4(wslot + 1, pb);
                }
            }

            #pragma unroll
            for (int k = 0; k < BLK; ++k) lbuf[k] = ln[k];
            __syncthreads();
        }
    } else {
        // ================= top CTA: levels 7..13, 64 threads x up to 2 reaches =====
        const bool hasA = (tid < 64);             // reach A: level 7, element tid
        const bool hasB = (tid < 63);             // reach B: levels 8..13
        int mm = 1, jB = 0;
        if (hasB) {
            const unsigned u = 63 - tid;          // 1..63
            mm = __clz(u) - 25;                   // 1..6 -> global level 7+mm
            jB = tid - (64 - (64 >> (mm - 1)));
        }
        const int  rA = 16256 + tid;              // level-7 offset 16384-128
        const int  lgB = 7 + mm;
        const int  rB = (16384 - (16384 >> lgB)) + jB;
        const int  skewB = mm;
        // children slots of reach B in sq: level 8 reads reach-A slots; deeper read B slots
        const int  cb = (mm == 1) ? (2 * jB)
                                  : (64 + (64 - (64 >> (mm - 2))) + 2 * jB);
        const bool is_outlet = (mm == 6) && hasB; // thread 62, level 13

        MCC cA = {}, cB = {};
        float QA = 0.f, IpA = 0.f, QB = 0.f, IpB = 0.f;
        float lbufA[BLK], lbufB[BLK];
        #pragma unroll
        for (int k = 0; k < BLK; ++k) { lbufA[k] = 0.f; lbufB[k] = 0.f; }
        const float* latpA = lat;
        const float* latpB = lat;
        if (hasA) {
            cA = mk_consts(rA, logn, lens, slp, wcs, wes, dcs, des);
            latpA = lat + rA;
            #pragma unroll
            for (int k = 0; k < BLK; ++k) lbufA[k] = __ldg(latpA + (size_t)k * NREACH);
        }
        if (hasB) {
            cB = mk_consts(rB, logn, lens, slp, wcs, wes, dcs, des);
            latpB = lat + rB;
        }

        uint4 pv00 = SENT4, pv01 = SENT4, pv10 = SENT4, pv11 = SENT4;
        if (hasA) {
            pv00 = ld_rlx4(&g_ring[2 * tid][0][0]);
            pv01 = ld_rlx4(&g_ring[2 * tid][0][1]);
            pv10 = ld_rlx4(&g_ring[2 * tid + 1][0][0]);
            pv11 = ld_rlx4(&g_ring[2 * tid + 1][0][1]);
        }

        for (int bi = 0; bi < ITER; ++bi) {
            const int tbA = bi;
            const int tbB = bi - skewB;
            const int p   = bi & 1;
            const bool runA = hasA && (tbA < NB);
            const bool runB = hasB && (tbB >= 0) && (tbB < NB);

            float lnA[BLK], lnB[BLK];
            #pragma unroll
            for (int k = 0; k < BLK; ++k) { lnA[k] = 0.f; lnB[k] = 0.f; }
            if (hasA && (tbA + 1) < NB) {
                const float* bp = latpA + (size_t)(BLK * (tbA + 1)) * NREACH;
                #pragma unroll
                for (int k = 0; k < BLK; ++k) lnA[k] = __ldg(bp + (size_t)k * NREACH);
            }
            if (hasB && (tbB + 1) >= 0 && (tbB + 1) < NB) {
                const float* bp = latpB + (size_t)(BLK * (tbB + 1)) * NREACH;
                #pragma unroll
                for (int k = 0; k < BLK; ++k) lnB[k] = __ldg(bp + (size_t)k * NREACH);
            }

            float csum[BLK];
            if (runA) {
                const int s = tbA & (RDEPTH - 1);
                uint4* c0 = &g_ring[2 * tid][s][0];
                uint4* c1 = &g_ring[2 * tid + 1][s][0];
                const uint4 v00 = wait_data4(c0,     pv00);
                const uint4 v01 = wait_data4(c0 + 1, pv01);
                const uint4 v10 = wait_data4(c1,     pv10);
                const uint4 v11 = wait_data4(c1 + 1, pv11);
                st_rlx4(c0,     SENT4); st_rlx4(c0 + 1, SENT4);
                st_rlx4(c1,     SENT4); st_rlx4(c1 + 1, SENT4);
                csum[0] = __uint_as_float(v00.x) + __uint_as_float(v10.x);
                csum[1] = __uint_as_float(v00.y) + __uint_as_float(v10.y);
                csum[2] = __uint_as_float(v00.z) + __uint_as_float(v10.z);
                csum[3] = __uint_as_float(v00.w) + __uint_as_float(v10.w);
                csum[4] = __uint_as_float(v01.x) + __uint_as_float(v11.x);
                csum[5] = __uint_as_float(v01.y) + __uint_as_float(v11.y);
                csum[6] = __uint_as_float(v01.z) + __uint_as_float(v11.z);
                csum[7] = __uint_as_float(v01.w) + __uint_as_float(v11.w);
                if (tbA + 1 < NB) {
                    const int s2 = (tbA + 1) & (RDEPTH - 1);
                    pv00 = ld_rlx4(&g_ring[2 * tid][s2][0]);
                    pv01 = ld_rlx4(&g_ring[2 * tid][s2][1]);
                    pv10 = ld_rlx4(&g_ring[2 * tid + 1][s2][0]);
                    pv11 = ld_rlx4(&g_ring[2 * tid + 1][s2][1]);
                }
            }

            #pragma unroll
            for (int k = 0; k < BLK; ++k) {
                if (runA) {
                    const float InewA = lbufA[k] + csum[k];
                    const float qA = mc_timestep(InewA, IpA, QA, cA);
                    QA = qA;
                    sq[p][k][tid] = qA;
                }
                if (runB) {
                    const float InewB = lbufB[k]
                        + sq[p ^ 1][k][cb] + sq[p ^ 1][k][cb + 1];
                    const float qB = mc_timestep(InewB, IpB, QB, cB);
                    QB = qB;
                    if (is_outlet) out[BLK * tbB + k] = qB;
                    else           sq[p][k][64 + tid] = qB;
                }
            }

            #pragma unroll
            for (int k = 0; k < BLK; ++k) { lbufA[k] = lnA[k]; lbufB[k] = lnB[k]; }
            __syncthreads();
        }
    }
}

extern "C" void kernel_launch(void* const* d_in, const int* in_sizes, int n_in,
                              void* d_out, int out_size) {
    const float* lat  = (const float*)d_in[0];
    const float* logn = (const float*)d_in[1];
    const float* lens = (const float*)d_in[2];
    const float* slp  = (const float*)d_in[3];
    const float* wcs  = (const float*)d_in[4];
    const float* wes  = (const float*)d_in[5];
    const float* dcs  = (const float*)d_in[6];
    const float* des  = (const float*)d_in[7];
    float* out = (float*)d_out;

    init_ring<<<(128 * RDEPTH * 8 + 255) / 256, 256>>>();
    route_kernel<<<129, 128>>>(lat, logn, lens, slp, wcs, wes, dcs, des, out);
}